// round 1
// baseline (speedup 1.0000x reference)
#include <cuda_runtime.h>
#include <cstddef>

// Problem constants (fixed by the reference)
#define BB 8
#define DD 32
#define NPIX 262144          // 512*512
#define KK 16

// Pass-1 tiling
#define P1_BLOCKS 32
#define P1_CHUNK  (NPIX / P1_BLOCKS)   // 8192 pixels per block
#define P1_STAGE  4096                 // labels staged per sync

// Pass-2 tiling
#define P2_BLOCKS 64
#define P2_CHUNK  (NPIX / P2_BLOCKS)   // 4096 pixels per block

// Scratch (no cudaMalloc allowed)
__device__ float g_sums[BB * KK * DD];
__device__ float g_counts[BB * KK];
__device__ float g_means[BB * KK * DD];

// ---------------------------------------------------------------------------
// Zero scratch + output (graph replays re-enter with dirty state)
// ---------------------------------------------------------------------------
__global__ void k_zero(float* out) {
    int tid = threadIdx.x;
    for (int j = tid; j < BB * KK * DD; j += blockDim.x) g_sums[j] = 0.0f;
    if (tid < BB * KK) g_counts[tid] = 0.0f;
    if (tid == 0) out[0] = 0.0f;
}

// ---------------------------------------------------------------------------
// Pass 1: per-image segment sums (sums[K][D]) and counts[K].
// Block = 512 threads = 16 warps; warp w owns feature d = dg*16 + w.
// Per-lane privatized smem accumulators -> conflict-free LDS/FADD/STS,
// no atomics in the hot loop.
// ---------------------------------------------------------------------------
__global__ __launch_bounds__(512) void k_pass1(const float* __restrict__ emb,
                                               const int* __restrict__ gt) {
    __shared__ float acc[16 * KK * 32];          // [w][k][lane]  32 KB
    __shared__ float cnt[KK * 32];               // [k][lane]      2 KB
    __shared__ unsigned char lab[P1_STAGE];      //                4 KB

    const int b  = blockIdx.z;
    const int dg = blockIdx.y;                   // d group: 0 or 1
    const int p0 = blockIdx.x * P1_CHUNK;
    const int tid = threadIdx.x;
    const int w   = tid >> 5;
    const int lane = tid & 31;
    const int d = dg * 16 + w;

    for (int j = tid; j < 16 * KK * 32; j += 512) acc[j] = 0.0f;
    if (tid < KK * 32) cnt[tid] = 0.0f;

    const float* eptr = emb + ((size_t)(b * DD + d)) * NPIX + p0;
    const int*   gptr = gt  + (size_t)b * NPIX + p0;
    const bool docnt = (dg == 0) && (w == 0);

    float* aw = acc + (w * KK) * 32 + lane;
    float* cw = cnt + lane;

    for (int s = 0; s < P1_CHUNK; s += P1_STAGE) {
        __syncthreads();
        for (int j = tid; j < P1_STAGE; j += 512)
            lab[j] = (unsigned char)gptr[s + j];
        __syncthreads();

        #pragma unroll 4
        for (int i = lane; i < P1_STAGE; i += 32) {
            float v = eptr[s + i];
            int k = (int)lab[i];
            aw[k * 32] += v;
            if (docnt) cw[k * 32] += 1.0f;
        }
    }
    __syncthreads();

    // Reduce each (k) row across lanes, one atomicAdd per (b,k,d) per block.
    for (int k = 0; k < KK; k++) {
        float v = acc[(w * KK + k) * 32 + lane];
        #pragma unroll
        for (int off = 16; off; off >>= 1)
            v += __shfl_down_sync(0xffffffffu, v, off);
        if (lane == 0) atomicAdd(&g_sums[(b * KK + k) * DD + d], v);
    }
    if (docnt) {
        for (int k = 0; k < KK; k++) {
            float v = cnt[k * 32 + lane];
            #pragma unroll
            for (int off = 16; off; off >>= 1)
                v += __shfl_down_sync(0xffffffffu, v, off);
            if (lane == 0) atomicAdd(&g_counts[b * KK + k], v);
        }
    }
}

// ---------------------------------------------------------------------------
// Finalize: means, pairwise push loss, regularization. One block per image.
// ---------------------------------------------------------------------------
__global__ __launch_bounds__(256) void k_finalize(float* out) {
    __shared__ float m[KK * 33];    // padded means
    __shared__ float cs[KK];
    __shared__ float red[256];

    const int b = blockIdx.x;
    const int tid = threadIdx.x;

    if (tid < KK) cs[tid] = fmaxf(g_counts[b * KK + tid], 1.0f);
    __syncthreads();

    for (int j = tid; j < KK * DD; j += 256) {
        int k = j / DD, d = j % DD;
        float mean = g_sums[(b * KK + k) * DD + d] / cs[k];
        g_means[(b * KK + k) * DD + d] = mean;
        m[k * 33 + d] = mean;
    }
    __syncthreads();

    // Pairwise hinge on cluster-mean distances: thread -> (i,j), upper tri only.
    const int i = tid >> 4;
    const int j = tid & 15;
    float contrib = 0.0f;
    if (tid < 256 && j > i) {
        float d2 = 0.0f;
        #pragma unroll
        for (int d = 0; d < DD; d++) {
            float df = m[i * 33 + d] - m[j * 33 + d];
            d2 = fmaf(df, df, d2);
        }
        float pd = sqrtf(d2);             // eye only affects diagonal; i<j safe
        float h = fmaxf(3.0f - pd, 0.0f); // 2 * DIST_THETA = 3.0
        contrib = h * h;
    }

    float reg = 0.0f;
    if (tid < KK) {
        float n2 = 0.0f;
        #pragma unroll
        for (int d = 0; d < DD; d++) {
            float v = m[tid * 33 + d];
            n2 = fmaf(v, v, n2);
        }
        reg = sqrtf(n2);
    }

    red[tid] = contrib * (1.0f / (KK * (KK - 1))) + 0.001f * reg * (1.0f / KK);
    __syncthreads();
    for (int off = 128; off; off >>= 1) {
        if (tid < off) red[tid] += red[tid + off];
        __syncthreads();
    }
    if (tid == 0) atomicAdd(out, red[0] * (1.0f / BB));
}

// ---------------------------------------------------------------------------
// Pass 2: per-pixel hinge variance loss, folded directly into the scalar.
// Thread-per-pixel; d loop fully unrolled; every LDG is a 128B line.
// ---------------------------------------------------------------------------
__global__ __launch_bounds__(256) void k_pass2(const float* __restrict__ emb,
                                               const int* __restrict__ gt,
                                               float* out) {
    __shared__ float m[KK * 33];
    __shared__ float wk[KK];
    __shared__ float red[8];

    const int b  = blockIdx.y;
    const int p0 = blockIdx.x * P2_CHUNK;
    const int tid = threadIdx.x;
    const int lane = tid & 31;
    const int w = tid >> 5;

    for (int j = tid; j < KK * DD; j += 256)
        m[(j / DD) * 33 + (j % DD)] = g_means[b * KK * DD + j];
    if (tid < KK)
        wk[tid] = 1.0f / ((float)KK * fmaxf(g_counts[b * KK + tid], 1.0f));
    __syncthreads();

    const float* ebase = emb + (size_t)b * DD * NPIX;
    const int*   gbase = gt + (size_t)b * NPIX;

    float lacc = 0.0f;
    for (int p = p0 + tid; p < p0 + P2_CHUNK; p += 256) {
        int k = gbase[p];
        const float* mk = m + k * 33;
        float d2 = 0.0f;
        #pragma unroll
        for (int d = 0; d < DD; d++) {
            float v = ebase[(size_t)d * NPIX + p];
            float df = v - mk[d];
            d2 = fmaf(df, df, d2);
        }
        float h = fmaxf(sqrtf(d2) - 0.5f, 0.0f);   // VAR_THETA = 0.5
        lacc = fmaf(h * h, wk[k], lacc);
    }

    #pragma unroll
    for (int off = 16; off; off >>= 1)
        lacc += __shfl_down_sync(0xffffffffu, lacc, off);
    if (lane == 0) red[w] = lacc;
    __syncthreads();
    if (tid == 0) {
        float s = 0.0f;
        #pragma unroll
        for (int i = 0; i < 8; i++) s += red[i];
        atomicAdd(out, s * (1.0f / BB));
    }
}

// ---------------------------------------------------------------------------
extern "C" void kernel_launch(void* const* d_in, const int* in_sizes, int n_in,
                              void* d_out, int out_size) {
    int ei = 0, gi = 1;
    // Defensive: identify inputs by size (embeddings = 67108864, gt = 2097152)
    if (n_in >= 2 && in_sizes[0] == BB * NPIX) { ei = 1; gi = 0; }

    const float* emb = (const float*)d_in[ei];
    const int*   gt  = (const int*)d_in[gi];
    float* out = (float*)d_out;

    k_zero<<<1, 512>>>(out);
    k_pass1<<<dim3(P1_BLOCKS, 2, BB), 512>>>(emb, gt);
    k_finalize<<<BB, 256>>>(out);
    k_pass2<<<dim3(P2_BLOCKS, BB), 256>>>(emb, gt, out);
}

// round 2
// speedup vs baseline: 1.1740x; 1.1740x over previous
#include <cuda_runtime.h>
#include <cstddef>

// Problem constants (fixed by the reference)
#define BB 8
#define DD 32
#define NPIX 262144          // 512*512
#define KK 16

// Pass-1 tiling: 64 pixel-blocks x 2 d-groups x 8 images = 1024 blocks
#define P1_BLOCKS 64
#define P1_CHUNK  (NPIX / P1_BLOCKS)   // 4096 pixels per block (single stage)

// Pass-2 tiling: one float4 (4 pixels) per thread
#define P2_TPB    256
#define P2_BLOCKS (NPIX / 4 / P2_TPB)  // 256 blocks per image

// Scratch (no cudaMalloc allowed)
__device__ float g_sums[BB * KK * DD];
__device__ float g_counts[BB * KK];
__device__ float g_means[BB * KK * DD];

// ---------------------------------------------------------------------------
// Zero scratch + output (graph replays re-enter with dirty state)
// ---------------------------------------------------------------------------
__global__ void k_zero(float* out) {
    int tid = threadIdx.x;
    for (int j = tid; j < BB * KK * DD; j += blockDim.x) g_sums[j] = 0.0f;
    if (tid < BB * KK) g_counts[tid] = 0.0f;
    if (tid == 0) out[0] = 0.0f;
}

// ---------------------------------------------------------------------------
// Pass 1: per-image segment sums (sums[K][D]) and counts[K].
// Block = 512 threads = 16 warps; warp w owns feature d = dg*16 + w.
// float4 loads -> 4 independent conflict-free smem RMW chains per iteration.
// ---------------------------------------------------------------------------
__global__ __launch_bounds__(512) void k_pass1(const float* __restrict__ emb,
                                               const int* __restrict__ gt) {
    __shared__ float acc[16 * KK * 32];          // [w][k][lane]  32 KB
    __shared__ float cnt[KK * 32];               // [k][lane]      2 KB
    __shared__ uchar4 lab4[P1_CHUNK / 4];        //                4 KB

    const int b  = blockIdx.z;
    const int dg = blockIdx.y;                   // d group: 0 or 1
    const int p0 = blockIdx.x * P1_CHUNK;
    const int tid = threadIdx.x;
    const int w   = tid >> 5;
    const int lane = tid & 31;
    const int d = dg * 16 + w;

    for (int j = tid; j < 16 * KK * 32; j += 512) acc[j] = 0.0f;
    if (tid < KK * 32) cnt[tid] = 0.0f;

    // Stage labels once (int4 -> uchar4)
    const int4* g4 = (const int4*)(gt + (size_t)b * NPIX + p0);
    for (int j = tid; j < P1_CHUNK / 4; j += 512) {
        int4 t = g4[j];
        lab4[j] = make_uchar4((unsigned char)t.x, (unsigned char)t.y,
                              (unsigned char)t.z, (unsigned char)t.w);
    }
    __syncthreads();

    const float4* e4 = (const float4*)(emb + ((size_t)(b * DD + d)) * NPIX + p0);
    const bool docnt = (dg == 0) && (w == 0);

    float* aw = acc + (w * KK) * 32 + lane;
    float* cw = cnt + lane;

    #pragma unroll 2
    for (int i = lane; i < P1_CHUNK / 4; i += 32) {
        float4 v = e4[i];
        uchar4 k4 = lab4[i];
        aw[(int)k4.x * 32] += v.x;
        aw[(int)k4.y * 32] += v.y;
        aw[(int)k4.z * 32] += v.z;
        aw[(int)k4.w * 32] += v.w;
        if (docnt) {
            cw[(int)k4.x * 32] += 1.0f;
            cw[(int)k4.y * 32] += 1.0f;
            cw[(int)k4.z * 32] += 1.0f;
            cw[(int)k4.w * 32] += 1.0f;
        }
    }
    __syncthreads();

    // Reduce each (k) row across lanes, one atomicAdd per (b,k,d) per block.
    for (int k = 0; k < KK; k++) {
        float v = acc[(w * KK + k) * 32 + lane];
        #pragma unroll
        for (int off = 16; off; off >>= 1)
            v += __shfl_down_sync(0xffffffffu, v, off);
        if (lane == 0) atomicAdd(&g_sums[(b * KK + k) * DD + d], v);
    }
    if (docnt) {
        for (int k = 0; k < KK; k++) {
            float v = cnt[k * 32 + lane];
            #pragma unroll
            for (int off = 16; off; off >>= 1)
                v += __shfl_down_sync(0xffffffffu, v, off);
            if (lane == 0) atomicAdd(&g_counts[b * KK + k], v);
        }
    }
}

// ---------------------------------------------------------------------------
// Finalize: means, pairwise push loss, regularization. One block per image.
// ---------------------------------------------------------------------------
__global__ __launch_bounds__(256) void k_finalize(float* out) {
    __shared__ float m[KK * 33];    // padded means
    __shared__ float cs[KK];
    __shared__ float red[256];

    const int b = blockIdx.x;
    const int tid = threadIdx.x;

    if (tid < KK) cs[tid] = fmaxf(g_counts[b * KK + tid], 1.0f);
    __syncthreads();

    for (int j = tid; j < KK * DD; j += 256) {
        int k = j / DD, d = j % DD;
        float mean = g_sums[(b * KK + k) * DD + d] / cs[k];
        g_means[(b * KK + k) * DD + d] = mean;
        m[k * 33 + d] = mean;
    }
    __syncthreads();

    // Pairwise hinge on cluster-mean distances: thread -> (i,j), upper tri only.
    const int i = tid >> 4;
    const int j = tid & 15;
    float contrib = 0.0f;
    if (j > i) {
        float d2 = 0.0f;
        #pragma unroll
        for (int d = 0; d < DD; d++) {
            float df = m[i * 33 + d] - m[j * 33 + d];
            d2 = fmaf(df, df, d2);
        }
        float pd = sqrtf(d2);             // i<j: diagonal eye irrelevant
        float h = fmaxf(3.0f - pd, 0.0f); // 2 * DIST_THETA = 3.0
        contrib = h * h;
    }

    float reg = 0.0f;
    if (tid < KK) {
        float n2 = 0.0f;
        #pragma unroll
        for (int d = 0; d < DD; d++) {
            float v = m[tid * 33 + d];
            n2 = fmaf(v, v, n2);
        }
        reg = sqrtf(n2);
    }

    red[tid] = contrib * (1.0f / (KK * (KK - 1))) + 0.001f * reg * (1.0f / KK);
    __syncthreads();
    for (int off = 128; off; off >>= 1) {
        if (tid < off) red[tid] += red[tid + off];
        __syncthreads();
    }
    if (tid == 0) atomicAdd(out, red[0] * (1.0f / BB));
}

// ---------------------------------------------------------------------------
// Pass 2: per-pixel hinge variance loss, folded directly into the scalar.
// One float4 (4 consecutive pixels) per thread; 32 LDG.128 per thread.
// ---------------------------------------------------------------------------
__global__ __launch_bounds__(P2_TPB) void k_pass2(const float* __restrict__ emb,
                                                  const int* __restrict__ gt,
                                                  float* out) {
    __shared__ float m[KK * 33];
    __shared__ float wk[KK];
    __shared__ float red[P2_TPB / 32];

    const int b  = blockIdx.y;
    const int tid = threadIdx.x;
    const int lane = tid & 31;
    const int w = tid >> 5;
    const int p4 = blockIdx.x * P2_TPB + tid;    // float4 index

    for (int j = tid; j < KK * DD; j += P2_TPB)
        m[(j / DD) * 33 + (j % DD)] = g_means[b * KK * DD + j];
    if (tid < KK)
        wk[tid] = 1.0f / ((float)KK * fmaxf(g_counts[b * KK + tid], 1.0f));
    __syncthreads();

    const float4* e4 = (const float4*)(emb + (size_t)b * DD * NPIX);
    const int4 kk = ((const int4*)(gt + (size_t)b * NPIX))[p4];

    const float* m0 = m + kk.x * 33;
    const float* m1 = m + kk.y * 33;
    const float* m2 = m + kk.z * 33;
    const float* m3 = m + kk.w * 33;

    float a0 = 0.0f, a1 = 0.0f, a2 = 0.0f, a3 = 0.0f;
    #pragma unroll
    for (int d = 0; d < DD; d++) {
        float4 v = e4[(size_t)d * (NPIX / 4) + p4];
        float t;
        t = v.x - m0[d]; a0 = fmaf(t, t, a0);
        t = v.y - m1[d]; a1 = fmaf(t, t, a1);
        t = v.z - m2[d]; a2 = fmaf(t, t, a2);
        t = v.w - m3[d]; a3 = fmaf(t, t, a3);
    }

    float h, lacc = 0.0f;
    h = fmaxf(sqrtf(a0) - 0.5f, 0.0f); lacc = fmaf(h * h, wk[kk.x], lacc);
    h = fmaxf(sqrtf(a1) - 0.5f, 0.0f); lacc = fmaf(h * h, wk[kk.y], lacc);
    h = fmaxf(sqrtf(a2) - 0.5f, 0.0f); lacc = fmaf(h * h, wk[kk.z], lacc);
    h = fmaxf(sqrtf(a3) - 0.5f, 0.0f); lacc = fmaf(h * h, wk[kk.w], lacc);

    #pragma unroll
    for (int off = 16; off; off >>= 1)
        lacc += __shfl_down_sync(0xffffffffu, lacc, off);
    if (lane == 0) red[w] = lacc;
    __syncthreads();
    if (tid == 0) {
        float s = 0.0f;
        #pragma unroll
        for (int i = 0; i < P2_TPB / 32; i++) s += red[i];
        atomicAdd(out, s * (1.0f / BB));
    }
}

// ---------------------------------------------------------------------------
extern "C" void kernel_launch(void* const* d_in, const int* in_sizes, int n_in,
                              void* d_out, int out_size) {
    int ei = 0, gi = 1;
    // Defensive: identify inputs by size (embeddings = 67108864, gt = 2097152)
    if (n_in >= 2 && in_sizes[0] == BB * NPIX) { ei = 1; gi = 0; }

    const float* emb = (const float*)d_in[ei];
    const int*   gt  = (const int*)d_in[gi];
    float* out = (float*)d_out;

    k_zero<<<1, 512>>>(out);
    k_pass1<<<dim3(P1_BLOCKS, 2, BB), 512>>>(emb, gt);
    k_finalize<<<BB, 256>>>(out);
    k_pass2<<<dim3(P2_BLOCKS, BB), P2_TPB>>>(emb, gt, out);
}